// round 3
// baseline (speedup 1.0000x reference)
#include <cuda_runtime.h>
#include <cuda_bf16.h>
#include <cstdint>

#define N_TOKENS 8192
#define D_MODEL  1024
#define D_FF     4096
#define TOPK     2
#define N_EXPERTS 8
#define CAP      4096
#define TOTAL    (N_TOKENS*TOPK)

// ---------------- device scratch ----------------
__device__ int   g_cnt_raw[N_EXPERTS];
__device__ int   g_cnt[N_EXPERTS];
__device__ int   g_rowtok[N_EXPERTS*CAP];
__device__ int   g_slotof[TOTAL];
__device__ float g_xr [(size_t)N_TOKENS*D_MODEL];
__device__ float g_w1t[(size_t)N_EXPERTS*D_FF*D_MODEL];
__device__ float g_w2t[(size_t)N_EXPERTS*D_FF*D_MODEL];
__device__ float g_w3t[(size_t)N_EXPERTS*D_MODEL*D_FF];
__device__ float g_G  [(size_t)N_EXPERTS*CAP*D_FF];
__device__ float g_Y  [(size_t)N_EXPERTS*CAP*D_MODEL];

// ---------------- helpers ----------------
__device__ __forceinline__ uint32_t smem_u32(const void* p){
    uint32_t a;
    asm("{ .reg .u64 t; cvta.to.shared.u64 t, %1; cvt.u32.u64 %0, t; }" : "=r"(a) : "l"(p));
    return a;
}
__device__ __forceinline__ float to_tf32(float v){
    uint32_t r; asm("cvt.rna.tf32.f32 %0, %1;" : "=r"(r) : "f"(v));
    return __uint_as_float(r);
}
__device__ __forceinline__ void cp16(uint32_t s, const void* g, uint32_t n){
    asm volatile("cp.async.cg.shared.global [%0], [%1], 16, %2;" :: "r"(s), "l"(g), "r"(n));
}
#define CP_COMMIT() asm volatile("cp.async.commit_group;" ::: "memory")
#define CP_WAIT(n)  asm volatile("cp.async.wait_group %0;" :: "n"(n) : "memory")

__device__ __forceinline__ void mma_tf32(float& c0, float& c1, float& c2, float& c3,
                                         uint32_t a0, uint32_t a1, uint32_t a2, uint32_t a3,
                                         uint32_t b0, uint32_t b1){
    asm volatile("mma.sync.aligned.m16n8k8.row.col.f32.tf32.tf32.f32 "
        "{%0,%1,%2,%3}, {%4,%5,%6,%7}, {%8,%9}, {%0,%1,%2,%3};"
        : "+f"(c0), "+f"(c1), "+f"(c2), "+f"(c3)
        : "r"(a0), "r"(a1), "r"(a2), "r"(a3), "r"(b0), "r"(b1));
}

// smem geometry: rows padded to 36 floats (144B: 16B-aligned, conflict-free frags)
#define ROW_F     36
#define TILE_F    (128*ROW_F)          // 4608 floats per (A or B) chunk
#define STAGE_F   (2*TILE_F)           // 9216 floats per stage
#define SMEM_BYTES (2*STAGE_F*4)       // 73728

// ---------------- routing ----------------
__global__ void route_init_kernel(){
    if (threadIdx.x < N_EXPERTS) g_cnt_raw[threadIdx.x] = 0;
}
__global__ void route_assign_kernel(const int* __restrict__ eidx){
    int i = blockIdx.x * blockDim.x + threadIdx.x;
    if (i >= TOTAL) return;
    int e = eidx[i] & (N_EXPERTS - 1);
    int pos = atomicAdd(&g_cnt_raw[e], 1);
    if (pos < CAP){ g_rowtok[e*CAP + pos] = i >> 1; g_slotof[i] = e*CAP + pos; }
    else g_slotof[i] = -1;
}
__global__ void route_fin_kernel(){
    if (threadIdx.x < N_EXPERTS){
        int c = g_cnt_raw[threadIdx.x];
        g_cnt[threadIdx.x] = c < CAP ? c : CAP;
    }
}
// ---------------- round x to tf32 ----------------
__global__ void round_x_kernel(const float* __restrict__ x){
    int i = blockIdx.x * blockDim.x + threadIdx.x;
    if (i >= N_TOKENS*D_MODEL/4) return;
    float4 v = ((const float4*)x)[i];
    v.x = to_tf32(v.x); v.y = to_tf32(v.y); v.z = to_tf32(v.z); v.w = to_tf32(v.w);
    ((float4*)g_xr)[i] = v;
}
// ---------------- batched transpose src[e][R][C] -> dst[e][C][R], tf32 ----------------
__global__ void transpose_kernel(const float* __restrict__ src, int sel, int R, int C){
    __shared__ float tile[32][33];
    float* dstb = (sel == 0) ? g_w1t : (sel == 1) ? g_w2t : g_w3t;
    int e = blockIdx.z;
    const float* s = src + (size_t)e*R*C;
    float* d = dstb + (size_t)e*R*C;
    int bx = blockIdx.x, by = blockIdx.y;
    int tx = threadIdx.x & 31, ty = threadIdx.x >> 5;   // 256 threads
    #pragma unroll
    for (int i = 0; i < 32; i += 8)
        tile[ty + i][tx] = s[(size_t)(by*32 + ty + i) * C + bx*32 + tx];
    __syncthreads();
    #pragma unroll
    for (int i = 0; i < 32; i += 8)
        d[(size_t)(bx*32 + ty + i) * R + by*32 + tx] = to_tf32(tile[tx][ty + i]);
}

// ---------------- unified mma.sync GEMM ----------------
// MODE 0: [h1|h2] = Xg @ interleaved[w1t,w2t]^T, SwiGLU -> g_G.  grid (64, 32, 8)
// MODE 1: Y = G @ w3t^T -> g_Y.                                  grid (8, 32, 8)
template<int MODE>
__global__ void __launch_bounds__(256, 2) gemm_kernel(){
    const int NCH = (MODE == 0) ? (D_MODEL/32) : (D_FF/32);
    int nt = blockIdx.x, mt = blockIdx.y, e = blockIdx.z;
    int cnt = g_cnt[e];
    if (mt*128 >= cnt) return;
    extern __shared__ float smem[];
    uint32_t sbase = smem_u32(smem);

    int tid = threadIdx.x;
    int wid = tid >> 5, lid = tid & 31;
    int wm = wid >> 1, wn = wid & 1;         // 4 x 2 warps, warp tile 32(m) x 64(n)
    int g = lid >> 2, t = lid & 3;

    // ---- per-thread load descriptors (fixed rows; advance by chunk) ----
    int r0 = tid >> 3;                        // base row (0..31), +32 per it
    int sc = tid & 7;                         // 16B segment within 128B row
    const float* aptr[4];
    uint32_t     apred[4];
    const float* bptr[4];
    #pragma unroll
    for (int it = 0; it < 4; it++){
        int row = r0 + it*32;
        if (MODE == 0){
            int grow = mt*128 + row;
            int tok = (grow < cnt) ? g_rowtok[e*CAP + grow] : -1;
            aptr[it]  = (tok >= 0) ? (g_xr + (size_t)tok*D_MODEL + sc*4) : g_xr;
            apred[it] = (tok >= 0) ? 16u : 0u;
        } else {
            aptr[it]  = g_G + ((size_t)(e*CAP + mt*128 + row))*D_FF + sc*4;
            apred[it] = 16u;
        }
        if (MODE == 0){
            const float* wb = (row & 1) ? g_w2t : g_w1t;
            bptr[it] = wb + ((size_t)e*D_FF + nt*64 + (row >> 1))*D_MODEL + sc*4;
        } else {
            bptr[it] = g_w3t + ((size_t)e*D_MODEL + nt*128 + row)*D_FF + sc*4;
        }
    }
    uint32_t asm0 = sbase + r0*144 + sc*16;             // + it*4608 + s*36864
    uint32_t bsm0 = asm0 + (uint32_t)(TILE_F*4);

    float c[2][8][4];
    #pragma unroll
    for (int mf = 0; mf < 2; mf++)
        #pragma unroll
        for (int nf = 0; nf < 8; nf++)
            #pragma unroll
            for (int i = 0; i < 4; i++) c[mf][nf][i] = 0.f;

    // prologue: chunk 0 -> stage 0
    #pragma unroll
    for (int it = 0; it < 4; it++){
        cp16(asm0 + it*4608u, aptr[it], apred[it]);
        cp16(bsm0 + it*4608u, bptr[it], 16u);
    }
    CP_COMMIT();

    #pragma unroll 1
    for (int kc = 0; kc < NCH; kc++){
        int s = kc & 1;
        if (kc + 1 < NCH){
            uint32_t so = (uint32_t)(((kc+1)&1) * STAGE_F * 4);
            #pragma unroll
            for (int it = 0; it < 4; it++){
                cp16(asm0 + so + it*4608u, aptr[it] + (kc+1)*32, apred[it]);
                cp16(bsm0 + so + it*4608u, bptr[it] + (kc+1)*32, 16u);
            }
            CP_COMMIT();
            CP_WAIT(1);
        } else {
            CP_WAIT(0);
        }
        __syncthreads();

        const float* As = smem + s*STAGE_F;
        const float* Bs = As + TILE_F;
        const float* ab = As + (wm*32 + g)*ROW_F + t;
        const float* bb = Bs + (wn*64 + g)*ROW_F + t;
        #pragma unroll
        for (int kk = 0; kk < 4; kk++){
            uint32_t a[2][4];
            #pragma unroll
            for (int mf = 0; mf < 2; mf++){
                a[mf][0] = __float_as_uint(ab[mf*16*ROW_F            + kk*8]);
                a[mf][1] = __float_as_uint(ab[mf*16*ROW_F + 8*ROW_F  + kk*8]);
                a[mf][2] = __float_as_uint(ab[mf*16*ROW_F            + kk*8 + 4]);
                a[mf][3] = __float_as_uint(ab[mf*16*ROW_F + 8*ROW_F  + kk*8 + 4]);
            }
            uint32_t b[8][2];
            #pragma unroll
            for (int nf = 0; nf < 8; nf++){
                b[nf][0] = __float_as_uint(bb[nf*8*ROW_F + kk*8]);
                b[nf][1] = __float_as_uint(bb[nf*8*ROW_F + kk*8 + 4]);
            }
            #pragma unroll
            for (int mf = 0; mf < 2; mf++)
                #pragma unroll
                for (int nf = 0; nf < 8; nf++)
                    mma_tf32(c[mf][nf][0], c[mf][nf][1], c[mf][nf][2], c[mf][nf][3],
                             a[mf][0], a[mf][1], a[mf][2], a[mf][3],
                             b[nf][0], b[nf][1]);
        }
        __syncthreads();
    }

    // ---- epilogue ----
    if (MODE == 0){
        // even local-n = h1, odd = h2; pair lives in (c[..][0],c[..][1]) / (c[..][2],c[..][3])
        #pragma unroll
        for (int mf = 0; mf < 2; mf++){
            #pragma unroll
            for (int i2 = 0; i2 < 2; i2++){
                int m = mt*128 + wm*32 + mf*16 + i2*8 + g;
                float* gd = g_G + ((size_t)(e*CAP + m))*D_FF + nt*64 + wn*32;
                #pragma unroll
                for (int nf = 0; nf < 8; nf++){
                    float h = c[mf][nf][i2*2 + 0];
                    float v = c[mf][nf][i2*2 + 1];
                    gd[nf*4 + t] = to_tf32(h * v / (1.f + __expf(-h)));
                }
            }
        }
    } else {
        #pragma unroll
        for (int mf = 0; mf < 2; mf++){
            #pragma unroll
            for (int i2 = 0; i2 < 2; i2++){
                int m = mt*128 + wm*32 + mf*16 + i2*8 + g;
                float* yd = g_Y + ((size_t)(e*CAP + m))*D_MODEL + nt*128 + wn*64;
                #pragma unroll
                for (int nf = 0; nf < 8; nf++){
                    float2 o = make_float2(c[mf][nf][i2*2 + 0], c[mf][nf][i2*2 + 1]);
                    *(float2*)(yd + nf*8 + 2*t) = o;
                }
            }
        }
    }
}

// ---------------- weighted top-k combine ----------------
__global__ void combine_kernel(const float* __restrict__ ew, float* __restrict__ out){
    int i = blockIdx.x * blockDim.x + threadIdx.x;
    if (i >= N_TOKENS*D_MODEL/4) return;
    int tok = i >> 8;
    int d4 = i & 255;
    float4 acc = make_float4(0.f,0.f,0.f,0.f);
    #pragma unroll
    for (int k = 0; k < TOPK; k++){
        int s = g_slotof[2*tok + k];
        if (s >= 0){
            float w = ew[2*tok + k];
            float4 v = ((const float4*)g_Y)[(size_t)s*(D_MODEL/4) + d4];
            acc.x += w*v.x; acc.y += w*v.y; acc.z += w*v.z; acc.w += w*v.w;
        }
    }
    ((float4*)out)[i] = acc;
}

extern "C" void kernel_launch(void* const* d_in, const int* in_sizes, int n_in,
                              void* d_out, int out_size) {
    const float* x   = (const float*)d_in[0];
    const int*   idx = (const int*)  d_in[1];
    const float* ew  = (const float*)d_in[2];
    const float* w1  = (const float*)d_in[3];
    const float* w2  = (const float*)d_in[4];
    const float* w3  = (const float*)d_in[5];
    float* out = (float*)d_out;

    cudaFuncSetAttribute(gemm_kernel<0>, cudaFuncAttributeMaxDynamicSharedMemorySize, SMEM_BYTES);
    cudaFuncSetAttribute(gemm_kernel<1>, cudaFuncAttributeMaxDynamicSharedMemorySize, SMEM_BYTES);

    route_init_kernel<<<1, 32>>>();
    route_assign_kernel<<<TOTAL/256, 256>>>(idx);
    route_fin_kernel<<<1, 32>>>();
    round_x_kernel<<<(N_TOKENS*D_MODEL/4)/256, 256>>>(x);

    transpose_kernel<<<dim3(D_FF/32,    D_MODEL/32, N_EXPERTS), 256>>>(w1, 0, D_MODEL, D_FF);
    transpose_kernel<<<dim3(D_FF/32,    D_MODEL/32, N_EXPERTS), 256>>>(w2, 1, D_MODEL, D_FF);
    transpose_kernel<<<dim3(D_MODEL/32, D_FF/32,    N_EXPERTS), 256>>>(w3, 2, D_FF, D_MODEL);

    gemm_kernel<0><<<dim3(D_FF/64,    CAP/128, N_EXPERTS), 256, SMEM_BYTES>>>();
    gemm_kernel<1><<<dim3(D_MODEL/128, CAP/128, N_EXPERTS), 256, SMEM_BYTES>>>();

    combine_kernel<<<(N_TOKENS*D_MODEL/4)/256, 256>>>(ew, out);
}

// round 4
// speedup vs baseline: 1.8373x; 1.8373x over previous
#include <cuda_runtime.h>
#include <cuda_fp16.h>
#include <cstdint>

#define N_TOKENS 8192
#define D_MODEL  1024
#define D_FF     4096
#define TOPK     2
#define N_EXPERTS 8
#define CAP      4096
#define TOTAL    (N_TOKENS*TOPK)

// ---------------- device scratch ----------------
__device__ int    g_cnt_raw[N_EXPERTS];
__device__ int    g_cnt[N_EXPERTS];
__device__ int    g_rowtok[N_EXPERTS*CAP];
__device__ int    g_slotof[TOTAL];
__device__ __half g_xr [(size_t)N_TOKENS*D_MODEL];
__device__ __half g_w1t[(size_t)N_EXPERTS*D_FF*D_MODEL];
__device__ __half g_w2t[(size_t)N_EXPERTS*D_FF*D_MODEL];
__device__ __half g_w3t[(size_t)N_EXPERTS*D_MODEL*D_FF];
__device__ __half g_G  [(size_t)N_EXPERTS*CAP*D_FF];
__device__ float  g_Y  [(size_t)N_EXPERTS*CAP*D_MODEL];

// ---------------- helpers ----------------
__device__ __forceinline__ uint32_t smem_u32(const void* p){
    uint32_t a;
    asm("{ .reg .u64 t; cvta.to.shared.u64 t, %1; cvt.u32.u64 %0, t; }" : "=r"(a) : "l"(p));
    return a;
}
__device__ __forceinline__ void cp16(uint32_t s, const void* g, uint32_t n){
    asm volatile("cp.async.cg.shared.global [%0], [%1], 16, %2;" :: "r"(s), "l"(g), "r"(n));
}
#define CP_COMMIT() asm volatile("cp.async.commit_group;" ::: "memory")
#define CP_WAIT(n)  asm volatile("cp.async.wait_group %0;" :: "n"(n) : "memory")

__device__ __forceinline__ void mma_f16(float& c0, float& c1, float& c2, float& c3,
                                        uint32_t a0, uint32_t a1, uint32_t a2, uint32_t a3,
                                        uint32_t b0, uint32_t b1){
    asm volatile("mma.sync.aligned.m16n8k16.row.col.f32.f16.f16.f32 "
        "{%0,%1,%2,%3}, {%4,%5,%6,%7}, {%8,%9}, {%0,%1,%2,%3};"
        : "+f"(c0), "+f"(c1), "+f"(c2), "+f"(c3)
        : "r"(a0), "r"(a1), "r"(a2), "r"(a3), "r"(b0), "r"(b1));
}

// smem geometry (halfs): K-chunk 64, rows padded to 72 halfs (144B).
// frag-load bank = (4g+t) mod 32 -> conflict-free; 144 % 16 == 0 for cp.async.
#define ROW_H     72
#define TILE_H    (128*ROW_H)           // 9216 halfs = 18432 B per (A or B) tile
#define TILE_B    18432
#define STAGE_B   36864
#define SMEM_BYTES 73728

// ---------------- routing ----------------
__global__ void route_init_kernel(){
    if (threadIdx.x < N_EXPERTS) g_cnt_raw[threadIdx.x] = 0;
}
__global__ void route_assign_kernel(const int* __restrict__ eidx){
    int i = blockIdx.x * blockDim.x + threadIdx.x;
    if (i >= TOTAL) return;
    int e = eidx[i] & (N_EXPERTS - 1);
    int pos = atomicAdd(&g_cnt_raw[e], 1);
    if (pos < CAP){ g_rowtok[e*CAP + pos] = i >> 1; g_slotof[i] = e*CAP + pos; }
    else g_slotof[i] = -1;
}
__global__ void route_fin_kernel(){
    if (threadIdx.x < N_EXPERTS){
        int c = g_cnt_raw[threadIdx.x];
        g_cnt[threadIdx.x] = c < CAP ? c : CAP;
    }
}
// ---------------- x -> fp16 ----------------
__global__ void round_x_kernel(const float* __restrict__ x){
    int i = blockIdx.x * blockDim.x + threadIdx.x;
    if (i >= N_TOKENS*D_MODEL/4) return;
    float4 v = ((const float4*)x)[i];
    __half2 lo = __halves2half2(__float2half_rn(v.x), __float2half_rn(v.y));
    __half2 hi = __halves2half2(__float2half_rn(v.z), __float2half_rn(v.w));
    ((__half2*)g_xr)[2*i]   = lo;
    ((__half2*)g_xr)[2*i+1] = hi;
}
// ---------------- batched transpose src[e][R][C] -> dst[e][C][R], fp16 ----------------
__global__ void transpose_kernel(const float* __restrict__ src, int sel, int R, int C){
    __shared__ float tile[32][33];
    __half* dstb = (sel == 0) ? g_w1t : (sel == 1) ? g_w2t : g_w3t;
    int e = blockIdx.z;
    const float* s = src + (size_t)e*R*C;
    __half* d = dstb + (size_t)e*R*C;
    int bx = blockIdx.x, by = blockIdx.y;
    int tx = threadIdx.x & 31, ty = threadIdx.x >> 5;   // 256 threads
    #pragma unroll
    for (int i = 0; i < 32; i += 8)
        tile[ty + i][tx] = s[(size_t)(by*32 + ty + i) * C + bx*32 + tx];
    __syncthreads();
    #pragma unroll
    for (int i = 0; i < 32; i += 8)
        d[(size_t)(bx*32 + ty + i) * R + by*32 + tx] = __float2half_rn(tile[tx][ty + i]);
}

// ---------------- unified fp16 mma.sync GEMM ----------------
// MODE 0: [h1|h2] = Xg @ interleaved[w1t,w2t]^T, SwiGLU -> g_G (half). grid (64, 32, 8)
// MODE 1: Y = G @ w3t^T -> g_Y (float).                               grid (8, 32, 8)
template<int MODE>
__global__ void __launch_bounds__(256, 2) gemm_kernel(){
    const int NCH = (MODE == 0) ? (D_MODEL/64) : (D_FF/64);   // K / 64
    int nt = blockIdx.x, mt = blockIdx.y, e = blockIdx.z;
    int cnt = g_cnt[e];
    if (mt*128 >= cnt) return;
    extern __shared__ __half smh[];
    uint32_t sbase = smem_u32(smh);

    int tid = threadIdx.x;
    int wid = tid >> 5, lid = tid & 31;
    int wm = wid >> 1, wn = wid & 1;         // 4 x 2 warps, warp tile 32(m) x 64(n)
    int g = lid >> 2, t = lid & 3;

    // ---- per-thread load descriptors: row r0+32*it, 16B segment sc ----
    int r0 = tid >> 3;                        // 0..31
    int sc = tid & 7;                         // 0..7  (8 halfs each)
    const __half* aptr[4];
    uint32_t      apred[4];
    const __half* bptr[4];
    #pragma unroll
    for (int it = 0; it < 4; it++){
        int row = r0 + it*32;
        if (MODE == 0){
            int grow = mt*128 + row;
            int tok = (grow < cnt) ? g_rowtok[e*CAP + grow] : -1;
            aptr[it]  = (tok >= 0) ? (g_xr + (size_t)tok*D_MODEL + sc*8) : g_xr;
            apred[it] = (tok >= 0) ? 16u : 0u;
        } else {
            aptr[it]  = g_G + ((size_t)(e*CAP + mt*128 + row))*D_FF + sc*8;
            apred[it] = 16u;
        }
        if (MODE == 0){
            const __half* wb = (row & 1) ? g_w2t : g_w1t;
            bptr[it] = wb + ((size_t)e*D_FF + nt*64 + (row >> 1))*D_MODEL + sc*8;
        } else {
            bptr[it] = g_w3t + ((size_t)e*D_MODEL + nt*128 + row)*D_FF + sc*8;
        }
    }
    uint32_t asm0 = sbase + (uint32_t)r0*144u + (uint32_t)sc*16u;  // + it*4608 + s*STAGE_B
    uint32_t bsm0 = asm0 + (uint32_t)TILE_B;

    float c[2][8][4];
    #pragma unroll
    for (int mf = 0; mf < 2; mf++)
        #pragma unroll
        for (int nf = 0; nf < 8; nf++)
            #pragma unroll
            for (int i = 0; i < 4; i++) c[mf][nf][i] = 0.f;

    // prologue: chunk 0 -> stage 0  (A rows: 4 segs of first 64 halfs? no: 64 halfs = 128B = 8 segs)
    #pragma unroll
    for (int it = 0; it < 4; it++){
        cp16(asm0 + it*4608u, aptr[it], apred[it]);
        cp16(bsm0 + it*4608u, bptr[it], 16u);
    }
    CP_COMMIT();

    #pragma unroll 1
    for (int kc = 0; kc < NCH; kc++){
        int s = kc & 1;
        if (kc + 1 < NCH){
            uint32_t so = (uint32_t)(((kc+1)&1) * STAGE_B);
            #pragma unroll
            for (int it = 0; it < 4; it++){
                cp16(asm0 + so + it*4608u, aptr[it] + (size_t)(kc+1)*64, apred[it]);
                cp16(bsm0 + so + it*4608u, bptr[it] + (size_t)(kc+1)*64, 16u);
            }
            CP_COMMIT();
            CP_WAIT(1);
        } else {
            CP_WAIT(0);
        }
        __syncthreads();

        const __half* As = smh + (s ? STAGE_B/2 : 0);
        const __half* Bs = As + TILE_H;
        const __half* ab = As + (wm*32 + g)*ROW_H + 2*t;
        const __half* bb = Bs + (wn*64 + g)*ROW_H + 2*t;
        #pragma unroll
        for (int kk = 0; kk < 4; kk++){
            uint32_t a[2][4];
            #pragma unroll
            for (int mf = 0; mf < 2; mf++){
                const __half* p = ab + mf*16*ROW_H + kk*16;
                a[mf][0] = *(const uint32_t*)(p);
                a[mf][1] = *(const uint32_t*)(p + 8*ROW_H);
                a[mf][2] = *(const uint32_t*)(p + 8);
                a[mf][3] = *(const uint32_t*)(p + 8*ROW_H + 8);
            }
            uint32_t b[8][2];
            #pragma unroll
            for (int nf = 0; nf < 8; nf++){
                const __half* p = bb + nf*8*ROW_H + kk*16;
                b[nf][0] = *(const uint32_t*)(p);
                b[nf][1] = *(const uint32_t*)(p + 8);
            }
            #pragma unroll
            for (int mf = 0; mf < 2; mf++)
                #pragma unroll
                for (int nf = 0; nf < 8; nf++)
                    mma_f16(c[mf][nf][0], c[mf][nf][1], c[mf][nf][2], c[mf][nf][3],
                            a[mf][0], a[mf][1], a[mf][2], a[mf][3],
                            b[nf][0], b[nf][1]);
        }
        __syncthreads();
    }

    // ---- epilogue (C frag: c0,c1 = row g cols 2t,2t+1; c2,c3 = row g+8) ----
    if (MODE == 0){
        // even local-n = h1 (w1), odd = h2 (w2): pair in (c[..][0], c[..][1]) etc.
        #pragma unroll
        for (int mf = 0; mf < 2; mf++){
            #pragma unroll
            for (int i2 = 0; i2 < 2; i2++){
                int m = mt*128 + wm*32 + mf*16 + i2*8 + g;
                __half* gd = g_G + ((size_t)(e*CAP + m))*D_FF + nt*64 + wn*32;
                #pragma unroll
                for (int nf = 0; nf < 8; nf++){
                    float h = c[mf][nf][i2*2 + 0];
                    float v = c[mf][nf][i2*2 + 1];
                    gd[nf*4 + t] = __float2half_rn(h * v / (1.f + __expf(-h)));
                }
            }
        }
    } else {
        #pragma unroll
        for (int mf = 0; mf < 2; mf++){
            #pragma unroll
            for (int i2 = 0; i2 < 2; i2++){
                int m = mt*128 + wm*32 + mf*16 + i2*8 + g;
                float* yd = g_Y + ((size_t)(e*CAP + m))*D_MODEL + nt*128 + wn*64;
                #pragma unroll
                for (int nf = 0; nf < 8; nf++){
                    float2 o = make_float2(c[mf][nf][i2*2 + 0], c[mf][nf][i2*2 + 1]);
                    *(float2*)(yd + nf*8 + 2*t) = o;
                }
            }
        }
    }
}

// ---------------- weighted top-k combine ----------------
__global__ void combine_kernel(const float* __restrict__ ew, float* __restrict__ out){
    int i = blockIdx.x * blockDim.x + threadIdx.x;
    if (i >= N_TOKENS*D_MODEL/4) return;
    int tok = i >> 8;
    int d4 = i & 255;
    float4 acc = make_float4(0.f,0.f,0.f,0.f);
    #pragma unroll
    for (int k = 0; k < TOPK; k++){
        int s = g_slotof[2*tok + k];
        if (s >= 0){
            float w = ew[2*tok + k];
            float4 v = ((const float4*)g_Y)[(size_t)s*(D_MODEL/4) + d4];
            acc.x += w*v.x; acc.y += w*v.y; acc.z += w*v.z; acc.w += w*v.w;
        }
    }
    ((float4*)out)[i] = acc;
}

extern "C" void kernel_launch(void* const* d_in, const int* in_sizes, int n_in,
                              void* d_out, int out_size) {
    const float* x   = (const float*)d_in[0];
    const int*   idx = (const int*)  d_in[1];
    const float* ew  = (const float*)d_in[2];
    const float* w1  = (const float*)d_in[3];
    const float* w2  = (const float*)d_in[4];
    const float* w3  = (const float*)d_in[5];
    float* out = (float*)d_out;

    cudaFuncSetAttribute(gemm_kernel<0>, cudaFuncAttributeMaxDynamicSharedMemorySize, SMEM_BYTES);
    cudaFuncSetAttribute(gemm_kernel<1>, cudaFuncAttributeMaxDynamicSharedMemorySize, SMEM_BYTES);

    route_init_kernel<<<1, 32>>>();
    route_assign_kernel<<<TOTAL/256, 256>>>(idx);
    route_fin_kernel<<<1, 32>>>();
    round_x_kernel<<<(N_TOKENS*D_MODEL/4)/256, 256>>>(x);

    transpose_kernel<<<dim3(D_FF/32,    D_MODEL/32, N_EXPERTS), 256>>>(w1, 0, D_MODEL, D_FF);
    transpose_kernel<<<dim3(D_FF/32,    D_MODEL/32, N_EXPERTS), 256>>>(w2, 1, D_MODEL, D_FF);
    transpose_kernel<<<dim3(D_MODEL/32, D_FF/32,    N_EXPERTS), 256>>>(w3, 2, D_FF, D_MODEL);

    gemm_kernel<0><<<dim3(D_FF/64,     CAP/128, N_EXPERTS), 256, SMEM_BYTES>>>();
    gemm_kernel<1><<<dim3(D_MODEL/128, CAP/128, N_EXPERTS), 256, SMEM_BYTES>>>();

    combine_kernel<<<(N_TOKENS*D_MODEL/4)/256, 256>>>(ew, out);
}

// round 5
// speedup vs baseline: 2.2293x; 1.2133x over previous
#include <cuda_runtime.h>
#include <cuda_fp16.h>
#include <cstdint>

#define N_TOKENS 8192
#define D_MODEL  1024
#define D_FF     4096
#define TOPK     2
#define N_EXPERTS 8
#define CAP      4096
#define TOTAL    (N_TOKENS*TOPK)

// ---------------- device scratch ----------------
__device__ int    g_cnt_raw[N_EXPERTS];
__device__ int    g_cnt[N_EXPERTS];
__device__ int    g_rowtok[N_EXPERTS*CAP];
__device__ int    g_slotof[TOTAL];
__device__ __half g_xr [(size_t)N_TOKENS*D_MODEL];
__device__ __half g_w1t[(size_t)N_EXPERTS*D_FF*D_MODEL];
__device__ __half g_w2t[(size_t)N_EXPERTS*D_FF*D_MODEL];
__device__ __half g_w3t[(size_t)N_EXPERTS*D_MODEL*D_FF];
__device__ __half g_G  [(size_t)N_EXPERTS*CAP*D_FF];
__device__ float  g_Y  [(size_t)N_EXPERTS*CAP*D_MODEL];

// ---------------- helpers ----------------
__device__ __forceinline__ uint32_t smem_u32(const void* p){
    uint32_t a;
    asm("{ .reg .u64 t; cvta.to.shared.u64 t, %1; cvt.u32.u64 %0, t; }" : "=r"(a) : "l"(p));
    return a;
}
__device__ __forceinline__ void cp16(uint32_t s, const void* g, uint32_t n){
    asm volatile("cp.async.cg.shared.global [%0], [%1], 16, %2;" :: "r"(s), "l"(g), "r"(n));
}
#define CP_COMMIT() asm volatile("cp.async.commit_group;" ::: "memory")
#define CP_WAIT(n)  asm volatile("cp.async.wait_group %0;" :: "n"(n) : "memory")

__device__ __forceinline__ void ldsm4(uint32_t& r0, uint32_t& r1, uint32_t& r2, uint32_t& r3, uint32_t a){
    asm volatile("ldmatrix.sync.aligned.m8n8.x4.shared.b16 {%0,%1,%2,%3}, [%4];"
        : "=r"(r0), "=r"(r1), "=r"(r2), "=r"(r3) : "r"(a));
}
__device__ __forceinline__ void mma_f16(float& c0, float& c1, float& c2, float& c3,
                                        uint32_t a0, uint32_t a1, uint32_t a2, uint32_t a3,
                                        uint32_t b0, uint32_t b1){
    asm volatile("mma.sync.aligned.m16n8k16.row.col.f32.f16.f16.f32 "
        "{%0,%1,%2,%3}, {%4,%5,%6,%7}, {%8,%9}, {%0,%1,%2,%3};"
        : "+f"(c0), "+f"(c1), "+f"(c2), "+f"(c3)
        : "r"(a0), "r"(a1), "r"(a2), "r"(a3), "r"(b0), "r"(b1));
}

// smem: rows of 64 halfs = 128B, XOR swizzle on 16B segs: phys = sc ^ (row&7)
// stage = A(128x128B=16K) + B(16K) = 32KB; 3 stages = 96KB
#define STAGE_B   32768
#define B_OFF     16384
#define SMEM_BYTES 98304

// ---------------- routing ----------------
__global__ void route_init_kernel(){
    if (threadIdx.x < N_EXPERTS) g_cnt_raw[threadIdx.x] = 0;
}
__global__ void route_assign_kernel(const int* __restrict__ eidx){
    int i = blockIdx.x * blockDim.x + threadIdx.x;
    if (i >= TOTAL) return;
    int e = eidx[i] & (N_EXPERTS - 1);
    int pos = atomicAdd(&g_cnt_raw[e], 1);
    if (pos < CAP){ g_rowtok[e*CAP + pos] = i >> 1; g_slotof[i] = e*CAP + pos; }
    else g_slotof[i] = -1;
}
__global__ void route_fin_kernel(){
    if (threadIdx.x < N_EXPERTS){
        int c = g_cnt_raw[threadIdx.x];
        g_cnt[threadIdx.x] = c < CAP ? c : CAP;
    }
}
// ---------------- x -> fp16 ----------------
__global__ void round_x_kernel(const float* __restrict__ x){
    int i = blockIdx.x * blockDim.x + threadIdx.x;
    if (i >= N_TOKENS*D_MODEL/4) return;
    float4 v = ((const float4*)x)[i];
    ((__half2*)g_xr)[2*i]   = __halves2half2(__float2half_rn(v.x), __float2half_rn(v.y));
    ((__half2*)g_xr)[2*i+1] = __halves2half2(__float2half_rn(v.z), __float2half_rn(v.w));
}
// ---------------- batched transpose src[e][R][C] -> dst[e][C][R], fp16 ----------------
__global__ void transpose_kernel(const float* __restrict__ src, int sel, int R, int C){
    __shared__ float tile[32][33];
    __half* dstb = (sel == 0) ? g_w1t : (sel == 1) ? g_w2t : g_w3t;
    int e = blockIdx.z;
    const float* s = src + (size_t)e*R*C;
    __half* d = dstb + (size_t)e*R*C;
    int bx = blockIdx.x, by = blockIdx.y;
    int tx = threadIdx.x & 31, ty = threadIdx.x >> 5;
    #pragma unroll
    for (int i = 0; i < 32; i += 8)
        tile[ty + i][tx] = s[(size_t)(by*32 + ty + i) * C + bx*32 + tx];
    __syncthreads();
    #pragma unroll
    for (int i = 0; i < 32; i += 8)
        d[(size_t)(bx*32 + ty + i) * R + by*32 + tx] = __float2half_rn(tile[tx][ty + i]);
}

// ---------------- fp16 mma.sync GEMM: CTA 128x128, 4 warps (2x2) of 64x64 ----------------
// MODE 0: [h1|h2] = Xg @ interleaved[w1t,w2t]^T, SwiGLU -> g_G. grid (64, 32, 8)
// MODE 1: Y = G @ w3t^T -> g_Y.                                 grid (8, 32, 8)
template<int MODE>
__global__ void __launch_bounds__(128, 2) gemm_kernel(){
    const int NCH = (MODE == 0) ? (D_MODEL/64) : (D_FF/64);
    int nt = blockIdx.x, mt = blockIdx.y, e = blockIdx.z;
    int cnt = g_cnt[e];
    if (mt*128 >= cnt) return;
    extern __shared__ char smem[];
    uint32_t sbase = smem_u32(smem);

    int tid = threadIdx.x;
    int wid = tid >> 5, lid = tid & 31;
    int wm = wid >> 1, wn = wid & 1;          // 2x2 warps, warp tile 64(m) x 64(n)
    int g = lid >> 2, t = lid & 3;

    // ---- cp.async source descriptors: thread handles rows r0+16*it, seg sc ----
    int r0 = tid >> 3;                         // 0..15
    int sc = tid & 7;                          // 16B segment
    const char* abase;
    uint32_t aoff[8];                          // byte offsets (u32), MODE0: token-gathered
    uint32_t amask = 0;
    const __half* bbase;
    size_t bstride;
    if (MODE == 0){
        abase = (const char*)g_xr;
        #pragma unroll
        for (int it = 0; it < 8; it++){
            int grow = mt*128 + r0 + it*16;
            int tok = (grow < cnt) ? g_rowtok[e*CAP + grow] : -1;
            aoff[it] = (tok >= 0) ? ((uint32_t)tok*(D_MODEL*2) + sc*16) : 0;
            if (tok >= 0) amask |= (1u << it);
        }
        const __half* wb = (r0 & 1) ? g_w2t : g_w1t;
        bbase = wb + ((size_t)e*D_FF + nt*64 + (r0 >> 1))*D_MODEL + sc*8;
        bstride = (size_t)8*D_MODEL;
    } else {
        abase = (const char*)(g_G + ((size_t)(e*CAP + mt*128 + r0))*D_FF + sc*8);
        #pragma unroll
        for (int it = 0; it < 8; it++){ aoff[it] = (uint32_t)it*16*D_FF*2; amask |= (1u<<it); }
        bbase = g_w3t + ((size_t)e*D_MODEL + nt*128 + r0)*D_FF + sc*8;
        bstride = (size_t)16*D_FF;
    }
    // smem dst for this thread's cp rows (stage-relative), swizzled
    uint32_t adst[8], bdst[8];
    #pragma unroll
    for (int it = 0; it < 8; it++){
        uint32_t row = (uint32_t)(r0 + it*16);
        uint32_t seg = ((uint32_t)sc ^ (row & 7u)) << 4;
        adst[it] = sbase + row*128u + seg;
        bdst[it] = sbase + B_OFF + row*128u + seg;
    }
    // ldmatrix lane base addresses (stage-relative), phys = base ^ (sl<<4)
    uint32_t albase[4], blbase[4];
    #pragma unroll
    for (int mf = 0; mf < 4; mf++){
        uint32_t row = (uint32_t)(wm*64 + mf*16 + (lid & 15));
        albase[mf] = sbase + row*128u + ((row & 7u) << 4);
    }
    #pragma unroll
    for (int j = 0; j < 4; j++){
        uint32_t row = (uint32_t)(wn*64 + j*16 + (lid & 7) + ((lid >> 4) & 1)*8);
        blbase[j] = sbase + B_OFF + row*128u + ((row & 7u) << 4);
    }
    uint32_t a_sl_hi = (uint32_t)(lid >> 4);        // A: sl = 2kk + (lid>>4)
    uint32_t b_sl_hi = (uint32_t)((lid >> 3) & 1);  // B: sl = 2kk + ((lid>>3)&1)

    float c[4][8][4];
    #pragma unroll
    for (int mf = 0; mf < 4; mf++)
        #pragma unroll
        for (int nf = 0; nf < 8; nf++)
            #pragma unroll
            for (int i = 0; i < 4; i++) c[mf][nf][i] = 0.f;

    // ---- prologue: chunks 0,1 into stages 0,1 ----
    #pragma unroll
    for (int pc = 0; pc < 2; pc++){
        uint32_t so = pc*STAGE_B;
        #pragma unroll
        for (int it = 0; it < 8; it++){
            cp16(adst[it] + so, abase + aoff[it] + (size_t)pc*128, ((amask>>it)&1) ? 16u : 0u);
            cp16(bdst[it] + so, bbase + (size_t)it*bstride + pc*64, 16u);
        }
        CP_COMMIT();
    }

    #pragma unroll 1
    for (int kc = 0; kc < NCH; kc++){
        if (kc == NCH-1) { CP_WAIT(0); } else { CP_WAIT(1); }
        __syncthreads();
        if (kc + 2 < NCH){
            uint32_t so = ((kc+2)%3)*STAGE_B;
            #pragma unroll
            for (int it = 0; it < 8; it++){
                cp16(adst[it] + so, abase + aoff[it] + (size_t)(kc+2)*128, ((amask>>it)&1) ? 16u : 0u);
                cp16(bdst[it] + so, bbase + (size_t)it*bstride + (size_t)(kc+2)*64, 16u);
            }
            CP_COMMIT();
        }
        uint32_t so = (kc%3)*STAGE_B;
        #pragma unroll
        for (int kk = 0; kk < 4; kk++){
            uint32_t a[4][4];
            #pragma unroll
            for (int mf = 0; mf < 4; mf++){
                uint32_t sl = (uint32_t)(2*kk) + a_sl_hi;
                ldsm4(a[mf][0], a[mf][1], a[mf][2], a[mf][3], (albase[mf] ^ (sl<<4)) + so);
            }
            uint32_t b[8][2];
            #pragma unroll
            for (int j = 0; j < 4; j++){
                uint32_t sl = (uint32_t)(2*kk) + b_sl_hi;
                ldsm4(b[2*j][0], b[2*j][1], b[2*j+1][0], b[2*j+1][1], (blbase[j] ^ (sl<<4)) + so);
            }
            #pragma unroll
            for (int mf = 0; mf < 4; mf++)
                #pragma unroll
                for (int nf = 0; nf < 8; nf++)
                    mma_f16(c[mf][nf][0], c[mf][nf][1], c[mf][nf][2], c[mf][nf][3],
                            a[mf][0], a[mf][1], a[mf][2], a[mf][3],
                            b[nf][0], b[nf][1]);
        }
    }

    // ---- epilogue ----
    if (MODE == 0){
        #pragma unroll
        for (int mf = 0; mf < 4; mf++){
            #pragma unroll
            for (int i2 = 0; i2 < 2; i2++){
                int m = mt*128 + wm*64 + mf*16 + i2*8 + g;
                __half* gd = g_G + ((size_t)(e*CAP + m))*D_FF + nt*64 + wn*32;
                #pragma unroll
                for (int nf = 0; nf < 8; nf++){
                    float h = c[mf][nf][i2*2 + 0];
                    float v = c[mf][nf][i2*2 + 1];
                    gd[nf*4 + t] = __float2half_rn(h * v / (1.f + __expf(-h)));
                }
            }
        }
    } else {
        #pragma unroll
        for (int mf = 0; mf < 4; mf++){
            #pragma unroll
            for (int i2 = 0; i2 < 2; i2++){
                int m = mt*128 + wm*64 + mf*16 + i2*8 + g;
                float* yd = g_Y + ((size_t)(e*CAP + m))*D_MODEL + nt*128 + wn*64;
                #pragma unroll
                for (int nf = 0; nf < 8; nf++){
                    float2 o = make_float2(c[mf][nf][i2*2 + 0], c[mf][nf][i2*2 + 1]);
                    *(float2*)(yd + nf*8 + 2*t) = o;
                }
            }
        }
    }
}

// ---------------- weighted top-k combine ----------------
__global__ void combine_kernel(const float* __restrict__ ew, float* __restrict__ out){
    int i = blockIdx.x * blockDim.x + threadIdx.x;
    if (i >= N_TOKENS*D_MODEL/4) return;
    int tok = i >> 8;
    int d4 = i & 255;
    float4 acc = make_float4(0.f,0.f,0.f,0.f);
    #pragma unroll
    for (int k = 0; k < TOPK; k++){
        int s = g_slotof[2*tok + k];
        if (s >= 0){
            float w = ew[2*tok + k];
            float4 v = ((const float4*)g_Y)[(size_t)s*(D_MODEL/4) + d4];
            acc.x += w*v.x; acc.y += w*v.y; acc.z += w*v.z; acc.w += w*v.w;
        }
    }
    ((float4*)out)[i] = acc;
}

extern "C" void kernel_launch(void* const* d_in, const int* in_sizes, int n_in,
                              void* d_out, int out_size) {
    const float* x   = (const float*)d_in[0];
    const int*   idx = (const int*)  d_in[1];
    const float* ew  = (const float*)d_in[2];
    const float* w1  = (const float*)d_in[3];
    const float* w2  = (const float*)d_in[4];
    const float* w3  = (const float*)d_in[5];
    float* out = (float*)d_out;

    cudaFuncSetAttribute(gemm_kernel<0>, cudaFuncAttributeMaxDynamicSharedMemorySize, SMEM_BYTES);
    cudaFuncSetAttribute(gemm_kernel<1>, cudaFuncAttributeMaxDynamicSharedMemorySize, SMEM_BYTES);

    route_init_kernel<<<1, 32>>>();
    route_assign_kernel<<<TOTAL/256, 256>>>(idx);
    route_fin_kernel<<<1, 32>>>();
    round_x_kernel<<<(N_TOKENS*D_MODEL/4)/256, 256>>>(x);

    transpose_kernel<<<dim3(D_FF/32,    D_MODEL/32, N_EXPERTS), 256>>>(w1, 0, D_MODEL, D_FF);
    transpose_kernel<<<dim3(D_FF/32,    D_MODEL/32, N_EXPERTS), 256>>>(w2, 1, D_MODEL, D_FF);
    transpose_kernel<<<dim3(D_MODEL/32, D_FF/32,    N_EXPERTS), 256>>>(w3, 2, D_FF, D_MODEL);

    gemm_kernel<0><<<dim3(D_FF/64,     CAP/128, N_EXPERTS), 128, SMEM_BYTES>>>();
    gemm_kernel<1><<<dim3(D_MODEL/128, CAP/128, N_EXPERTS), 128, SMEM_BYTES>>>();

    combine_kernel<<<(N_TOKENS*D_MODEL/4)/256, 256>>>(ew, out);
}